// round 4
// baseline (speedup 1.0000x reference)
#include <cuda_runtime.h>
#include <cuda_bf16.h>
#include <float.h>
#include <stdint.h>

// VectorQuantize: z[16,256,32,32] f32, codebook[8192,256] f32
// out: zq[16,256,32,32] f32 (+ idx tail as f32)
// Fused: bf16 mma.sync GEMM over full K per CTA + running-min candidate capture
// -> exact fp32 refine of the tiny candidate set. No 256MB score matrix.

#define NPTS 16384
#define NC   256
#define NK   8192
#define ZQ_ELEMS 4194304
#define TM 128
#define TN 128
#define NTILE (NK / TN)        // 64 col tiles
#define MARGIN 5e-3f
#define MAXCAND 16

// ---------------- scratch ----------------
__device__ unsigned short g_ah[NPTS * NC];    // bf16(z)
__device__ unsigned short g_bh[NK * NC];      // bf16(-2cb)
__device__ float g_zf[NPTS * NC];             // fp32 z rows (refine)
__device__ float g_zn[NPTS];
__device__ float g_cn[NK];                    // |cb|^2 fp32
__device__ int g_ccnt[NPTS];
__device__ int g_cand[NPTS * MAXCAND];
__device__ int g_idx[NPTS];

// ---------------- smem layout (dynamic, 105KB) ----------------
#define SA_OFF    0          // A resident: 4 chunks x 16KB
#define SB_OFF    65536      // B double buffer: 2 x 16KB
#define SROWMIN   98304      // 128 x u32 (encoded fp32)
#define SCNT      98816      // 128 x int
#define SCAND     99328      // 128 x 16 x int
#define SMEM_SZ   107520

// ---------------- PTX helpers ----------------
__device__ __forceinline__ uint32_t smem_u32(const void* p) {
    uint32_t a;
    asm("{ .reg .u64 t; cvta.to.shared.u64 t, %1; cvt.u32.u64 %0, t; }" : "=r"(a) : "l"(p));
    return a;
}
#define CP_ASYNC16(sm, gp) \
    asm volatile("cp.async.cg.shared.global [%0], [%1], 16;" :: "r"(sm), "l"(gp) : "memory")
#define CP_COMMIT() asm volatile("cp.async.commit_group;" ::: "memory")
#define CP_WAIT(n)  asm volatile("cp.async.wait_group %0;" :: "n"(n) : "memory")
#define LDSM_X4(r0, r1, r2, r3, ad) \
    asm volatile("ldmatrix.sync.aligned.m8n8.x4.shared.b16 {%0,%1,%2,%3}, [%4];" \
                 : "=r"(r0), "=r"(r1), "=r"(r2), "=r"(r3) : "r"(ad))
#define MMA16816(d, a0, a1, a2, a3, b0, b1) \
    asm volatile("mma.sync.aligned.m16n8k16.row.col.f32.bf16.bf16.f32 " \
                 "{%0,%1,%2,%3}, {%4,%5,%6,%7}, {%8,%9}, {%0,%1,%2,%3};" \
                 : "+f"((d)[0]), "+f"((d)[1]), "+f"((d)[2]), "+f"((d)[3]) \
                 : "r"(a0), "r"(a1), "r"(a2), "r"(a3), "r"(b0), "r"(b1))

// order-preserving fp32 <-> u32
__device__ __forceinline__ uint32_t fenc(float f) {
    uint32_t b = __float_as_uint(f);
    return (b & 0x80000000u) ? ~b : (b | 0x80000000u);
}
__device__ __forceinline__ float fdec(uint32_t u) {
    uint32_t b = (u & 0x80000000u) ? (u & 0x7FFFFFFFu) : ~u;
    return __uint_as_float(b);
}

// ---------------- prep ----------------
__global__ void prep_cb(const float* __restrict__ cb) {
    int k = blockIdx.x, t = threadIdx.x;
    float v = cb[(size_t)k * NC + t];
    __nv_bfloat16 h = __float2bfloat16_rn(-2.0f * v);
    g_bh[k * NC + t] = *(unsigned short*)&h;
    __shared__ float red[256];
    red[t] = v * v;
    __syncthreads();
    for (int s = 128; s > 0; s >>= 1) { if (t < s) red[t] += red[t + s]; __syncthreads(); }
    if (t == 0) g_cn[k] = red[0];
}

__global__ void prep_z(const float* __restrict__ z) {
    int n = blockIdx.x * blockDim.x + threadIdx.x;
    int b = n >> 10, hw = n & 1023;
    const float* zp = z + (size_t)b * (NC * 1024) + hw;
    float acc = 0.f;
#pragma unroll 8
    for (int c = 0; c < NC; c++) {
        float v = zp[(size_t)c * 1024];
        g_zf[n * NC + c] = v;
        acc += v * v;
        __nv_bfloat16 h = __float2bfloat16_rn(v);
        g_ah[n * NC + c] = *(unsigned short*)&h;
    }
    g_zn[n] = acc;
}

// ---------------- fused GEMM + running argmin + candidate capture ----------------
__global__ void __launch_bounds__(256, 1) vq_gemm() {
    extern __shared__ char smem[];
    const uint32_t sb = smem_u32(smem);
    const int t = threadIdx.x;
    const int lane = t & 31, wid = t >> 5;
    const int warp_m = wid >> 1, warp_n = wid & 1;     // 4x2 warps, 32x64 each
    const int row0 = blockIdx.x * TM;

    uint32_t* rowmin = (uint32_t*)(smem + SROWMIN);
    int* scnt = (int*)(smem + SCNT);
    int* scand = (int*)(smem + SCAND);
    if (t < TM) { rowmin[t] = fenc(FLT_MAX); scnt[t] = 0; }

    // load A resident (128 rows x 256 k, 4 swizzled 16KB chunks)
    {
        const unsigned short* A = g_ah + (size_t)row0 * NC;
#pragma unroll
        for (int i = 0; i < 16; i++) {
            int e = i * 256 + t;                 // 0..4095
            int kc = e >> 10, rem = e & 1023;
            int r = rem >> 3, ck = rem & 7;
            uint32_t dst = sb + SA_OFF + kc * 16384 + r * 128 + ((ck * 16) ^ ((r & 7) * 16));
            CP_ASYNC16(dst, A + (size_t)r * NC + kc * 64 + ck * 8);
        }
        CP_COMMIT();
    }

    float d[2][8][4];
#pragma unroll
    for (int i = 0; i < 2; i++)
#pragma unroll
        for (int j = 0; j < 8; j++)
#pragma unroll
            for (int q = 0; q < 4; q++) d[i][j][q] = 0.f;

    // B chunk loader: chunk c covers tile ct=c>>2, k-chunk kc=c&3 (128 rows x 64 k)
    auto issueB = [&](int c) {
        int ct = c >> 2, kc = c & 3;
        const unsigned short* B = g_bh + (size_t)(ct * TN) * NC + kc * 64;
        uint32_t bb = sb + SB_OFF + (c & 1) * 16384;
#pragma unroll
        for (int i = 0; i < 4; i++) {
            int e = i * 256 + t;                 // 0..1023
            int r = e >> 3, ck = e & 7;
            CP_ASYNC16(bb + r * 128 + ((ck * 16) ^ ((r & 7) * 16)),
                       B + (size_t)r * NC + ck * 8);
        }
        CP_COMMIT();
    };

    issueB(0);

    const int NCHUNK = NTILE * 4;
    for (int c = 0; c < NCHUNK; c++) {
        CP_WAIT(0);
        __syncthreads();
        if (c + 1 < NCHUNK) issueB(c + 1);

        const uint32_t Ab = sb + SA_OFF + (c & 3) * 16384;
        const uint32_t Bb = sb + SB_OFF + (c & 1) * 16384;
#pragma unroll
        for (int ks = 0; ks < 4; ks++) {
            const int c2 = ks * 32 + (lane >> 4) * 16;
            uint32_t a[2][4];
#pragma unroll
            for (int mt = 0; mt < 2; mt++) {
                int row = warp_m * 32 + mt * 16 + (lane & 15);
                uint32_t ad = Ab + row * 128 + (c2 ^ ((row & 7) * 16));
                LDSM_X4(a[mt][0], a[mt][1], a[mt][2], a[mt][3], ad);
            }
            uint32_t bq[4][4];
#pragma unroll
            for (int np = 0; np < 4; np++) {
                int brow = warp_n * 64 + np * 16 + (lane & 15);
                uint32_t bd = Bb + brow * 128 + (c2 ^ ((brow & 7) * 16));
                LDSM_X4(bq[np][0], bq[np][1], bq[np][2], bq[np][3], bd);
            }
#pragma unroll
            for (int mt = 0; mt < 2; mt++)
#pragma unroll
                for (int np = 0; np < 4; np++) {
                    MMA16816(d[mt][np * 2],     a[mt][0], a[mt][1], a[mt][2], a[mt][3],
                             bq[np][0], bq[np][2]);
                    MMA16816(d[mt][np * 2 + 1], a[mt][0], a[mt][1], a[mt][2], a[mt][3],
                             bq[np][1], bq[np][3]);
                }
        }

        if ((c & 3) == 3) {
            // ---- epilogue for tile ct ----
            const int ct = c >> 2;
            const int col0 = ct * TN;
            const int g = lane >> 2, tig = lane & 3;
            float2 cn[8];
#pragma unroll
            for (int nt = 0; nt < 8; nt++) {
                int scol = col0 + warp_n * 64 + nt * 8 + 2 * tig;
                cn[nt].x = __ldg(&g_cn[scol]);
                cn[nt].y = __ldg(&g_cn[scol + 1]);
            }
            // pass 1: per-row mins -> smem atomicMin
#pragma unroll
            for (int mt = 0; mt < 2; mt++) {
                float mn0 = FLT_MAX, mn1 = FLT_MAX;
#pragma unroll
                for (int nt = 0; nt < 8; nt++) {
                    mn0 = fminf(mn0, fminf(d[mt][nt][0] + cn[nt].x, d[mt][nt][1] + cn[nt].y));
                    mn1 = fminf(mn1, fminf(d[mt][nt][2] + cn[nt].x, d[mt][nt][3] + cn[nt].y));
                }
                atomicMin(&rowmin[warp_m * 32 + mt * 16 + g],     fenc(mn0));
                atomicMin(&rowmin[warp_m * 32 + mt * 16 + g + 8], fenc(mn1));
            }
            __syncthreads();
            // pass 2: capture candidates within margin of running min
#pragma unroll
            for (int mt = 0; mt < 2; mt++) {
                const int r0 = warp_m * 32 + mt * 16 + g;
                const float th0 = fdec(rowmin[r0]) + MARGIN;
                const float th1 = fdec(rowmin[r0 + 8]) + MARGIN;
#pragma unroll
                for (int nt = 0; nt < 8; nt++) {
                    const int cbase = col0 + warp_n * 64 + nt * 8 + 2 * tig;
                    float v0 = d[mt][nt][0] + cn[nt].x;
                    float v1 = d[mt][nt][1] + cn[nt].y;
                    float v2 = d[mt][nt][2] + cn[nt].x;
                    float v3 = d[mt][nt][3] + cn[nt].y;
                    if (v0 <= th0) { int s = atomicAdd(&scnt[r0], 1);     if (s < MAXCAND) scand[r0 * MAXCAND + s] = cbase; }
                    if (v1 <= th0) { int s = atomicAdd(&scnt[r0], 1);     if (s < MAXCAND) scand[r0 * MAXCAND + s] = cbase + 1; }
                    if (v2 <= th1) { int s = atomicAdd(&scnt[r0 + 8], 1); if (s < MAXCAND) scand[(r0 + 8) * MAXCAND + s] = cbase; }
                    if (v3 <= th1) { int s = atomicAdd(&scnt[r0 + 8], 1); if (s < MAXCAND) scand[(r0 + 8) * MAXCAND + s] = cbase + 1; }
                }
            }
            // reset accumulators
#pragma unroll
            for (int i = 0; i < 2; i++)
#pragma unroll
                for (int j = 0; j < 8; j++)
#pragma unroll
                    for (int q = 0; q < 4; q++) d[i][j][q] = 0.f;
        }
    }
    __syncthreads();
    // flush candidate lists
    if (t < TM) g_ccnt[row0 + t] = min(scnt[t], MAXCAND);
#pragma unroll
    for (int i = 0; i < 8; i++) {
        int e = i * 256 + t;                     // 0..2047 = 128 rows x 16
        int r = e >> 4, s = e & 15;
        g_cand[(size_t)(row0 + r) * MAXCAND + s] = scand[r * MAXCAND + s];
    }
}

// ---------------- exact fp32 refine: 1 warp per row ----------------
__global__ void __launch_bounds__(256) vq_refine(const float* __restrict__ cb) {
    const int lane = threadIdx.x & 31;
    const int row = blockIdx.x * 8 + (threadIdx.x >> 5);
    const int cnt = g_ccnt[row];

    float z8[8];
#pragma unroll
    for (int i = 0; i < 8; i++) z8[i] = g_zf[(size_t)row * NC + lane * 8 + i];
    const float zn = g_zn[row];

    float bv = FLT_MAX;
    int bi = 0x7fffffff;
    for (int c = 0; c < cnt; c++) {
        const int k = g_cand[(size_t)row * MAXCAND + c];
        const float* cbr = cb + (size_t)k * NC + lane * 8;
        float s = 0.f;
#pragma unroll
        for (int i = 0; i < 8; i++) s = fmaf(z8[i], -2.0f * cbr[i], s);
#pragma unroll
        for (int o = 16; o > 0; o >>= 1) s += __shfl_xor_sync(0xffffffffu, s, o);
        float dd = (s + zn) + g_cn[k];
        if (dd < bv || (dd == bv && k < bi)) { bv = dd; bi = k; }
    }
    if (lane == 0) g_idx[row] = bi;
}

// ---------------- outputs ----------------
__global__ void vq_gather(const float* __restrict__ cb, float* __restrict__ out) {
    int o = blockIdx.x * blockDim.x + threadIdx.x;
    int w = o & 31;
    int h = (o >> 5) & 31;
    int c = (o >> 10) & 255;
    int b = o >> 18;
    int n = (b << 10) + (h << 5) + w;
    out[o] = cb[(size_t)g_idx[n] * NC + c];
}

__global__ void vq_idx_out(float* __restrict__ out) {
    int n = blockIdx.x * blockDim.x + threadIdx.x;
    out[ZQ_ELEMS + n] = (float)g_idx[n];
}

extern "C" void kernel_launch(void* const* d_in, const int* in_sizes, int n_in,
                              void* d_out, int out_size) {
    const float* z  = (const float*)d_in[0];
    const float* cb = (const float*)d_in[1];
    if (n_in >= 2 && in_sizes[0] == NK * NC && in_sizes[1] == NPTS * NC) {
        const float* tmp = z; z = cb; cb = tmp;
    }
    float* out = (float*)d_out;

    cudaFuncSetAttribute(vq_gemm, cudaFuncAttributeMaxDynamicSharedMemorySize, SMEM_SZ);

    prep_cb<<<NK, 256>>>(cb);
    prep_z<<<NPTS / 256, 256>>>(z);
    vq_gemm<<<NPTS / TM, 256, SMEM_SZ>>>();
    vq_refine<<<NPTS / 8, 256>>>(cb);
    vq_gather<<<ZQ_ELEMS / 256, 256>>>(cb, out);
    if (out_size >= ZQ_ELEMS + NPTS)
        vq_idx_out<<<NPTS / 256, 256>>>(out);
}

// round 5
// speedup vs baseline: 1.0469x; 1.0469x over previous
#include <cuda_runtime.h>
#include <cuda_bf16.h>
#include <float.h>
#include <stdint.h>

// VectorQuantize: z[16,256,32,32] f32, codebook[8192,256] f32
// coarse int8 mma.sync (s8 k32) GEMM -> bf16 scores -> margin scan + exact fp32 refine.

#define NPTS 16384
#define NC   256
#define NK   8192
#define ZQ_ELEMS 4194304
#define TM 128
#define TN 128
#define MARGIN 3.5e-2f

// ---------------- scratch ----------------
__device__ signed char g_az[NPTS * NC];       // int8(z / sz)
__device__ signed char g_bq[NK * NC];         // int8(-2cb / sb)
__device__ float g_zf[NPTS * NC];             // fp32 z rows (refine)
__device__ float g_zn[NPTS];
__device__ float g_cn[NK];                    // |cb|^2
__device__ unsigned short g_dist[(size_t)NPTS * NK];  // coarse scores bf16
__device__ int g_idx[NPTS];
__device__ unsigned g_maxz_bits;
__device__ unsigned g_maxcb_bits;
__device__ float g_sz, g_sb, g_ss;            // scales; ss = sz*sb

// ---------------- PTX helpers ----------------
__device__ __forceinline__ uint32_t smem_u32(const void* p) {
    uint32_t a;
    asm("{ .reg .u64 t; cvta.to.shared.u64 t, %1; cvt.u32.u64 %0, t; }" : "=r"(a) : "l"(p));
    return a;
}
#define CP_ASYNC16(sm, gp) \
    asm volatile("cp.async.cg.shared.global [%0], [%1], 16;" :: "r"(sm), "l"(gp) : "memory")
#define CP_COMMIT() asm volatile("cp.async.commit_group;" ::: "memory")
#define CP_WAIT(n)  asm volatile("cp.async.wait_group %0;" :: "n"(n) : "memory")
#define LDSM_X4(r0, r1, r2, r3, ad) \
    asm volatile("ldmatrix.sync.aligned.m8n8.x4.shared.b16 {%0,%1,%2,%3}, [%4];" \
                 : "=r"(r0), "=r"(r1), "=r"(r2), "=r"(r3) : "r"(ad))
// s8 k32 IMMA: fragments layout-compatible with b16 k16 ldmatrix loads
#define IMMA16832(d, a0, a1, a2, a3, b0, b1) \
    asm volatile("mma.sync.aligned.m16n8k32.row.col.s32.s8.s8.s32 " \
                 "{%0,%1,%2,%3}, {%4,%5,%6,%7}, {%8,%9}, {%0,%1,%2,%3};" \
                 : "+r"((d)[0]), "+r"((d)[1]), "+r"((d)[2]), "+r"((d)[3]) \
                 : "r"(a0), "r"(a1), "r"(a2), "r"(a3), "r"(b0), "r"(b1))

// ---------------- scale discovery ----------------
__global__ void k_init() { g_maxz_bits = 0; g_maxcb_bits = 0; }

__global__ void k_max(const float* __restrict__ z, const float* __restrict__ cb) {
    const int t = threadIdx.x, nth = gridDim.x * blockDim.x;
    const int gt = blockIdx.x * blockDim.x + t;
    float mz = 0.f, mc = 0.f;
    for (int i = gt; i < NPTS * NC; i += nth) mz = fmaxf(mz, fabsf(z[i]));
    for (int i = gt; i < NK * NC;  i += nth) mc = fmaxf(mc, fabsf(cb[i]));
    __shared__ float sz[256], sc[256];
    sz[t] = mz; sc[t] = mc;
    __syncthreads();
    for (int s = 128; s > 0; s >>= 1) {
        if (t < s) { sz[t] = fmaxf(sz[t], sz[t + s]); sc[t] = fmaxf(sc[t], sc[t + s]); }
        __syncthreads();
    }
    if (t == 0) {
        atomicMax(&g_maxz_bits, __float_as_uint(sz[0]));   // nonneg floats: bit order = value order
        atomicMax(&g_maxcb_bits, __float_as_uint(sc[0]));
    }
}

__global__ void k_scales() {
    float mz = __uint_as_float(g_maxz_bits);
    float mc = __uint_as_float(g_maxcb_bits);
    float sz = mz / 127.0f, sb = 2.0f * mc / 127.0f;
    g_sz = sz; g_sb = sb; g_ss = sz * sb;
}

// ---------------- prep ----------------
__global__ void prep_cb(const float* __restrict__ cb) {
    int k = blockIdx.x, t = threadIdx.x;
    float v = cb[(size_t)k * NC + t];
    float q = (-2.0f * v) / g_sb;
    g_bq[k * NC + t] = (signed char)__float2int_rn(q);
    __shared__ float red[256];
    red[t] = v * v;
    __syncthreads();
    for (int s = 128; s > 0; s >>= 1) { if (t < s) red[t] += red[t + s]; __syncthreads(); }
    if (t == 0) g_cn[k] = red[0];
}

__global__ void prep_z(const float* __restrict__ z) {
    int n = blockIdx.x * blockDim.x + threadIdx.x;
    int b = n >> 10, hw = n & 1023;
    const float* zp = z + (size_t)b * (NC * 1024) + hw;
    const float inv_sz = 1.0f / g_sz;
    float acc = 0.f;
#pragma unroll 8
    for (int c = 0; c < NC; c++) {
        float v = zp[(size_t)c * 1024];
        g_zf[n * NC + c] = v;
        acc += v * v;
        g_az[n * NC + c] = (signed char)__float2int_rn(v * inv_sz);
    }
    g_zn[n] = acc;
}

// ---------------- coarse GEMM: 128x128 CTA tile, 8 warps, IMMA s8 k32 ----------------
// smem: double-buffered A/B k128 slabs (16KB each). buf b: A @ b*32768, B @ +16384.
__device__ __forceinline__ void issue_loads(uint32_t sb_, int buf,
                                            const signed char* A, const signed char* B,
                                            int kchunk, int t) {
    uint32_t ab = sb_ + buf * 32768;
    uint32_t bb = ab + 16384;
#pragma unroll
    for (int i = 0; i < 4; i++) {
        int e = i * 256 + t;
        int r = e >> 3, ck = e & 7;          // row 0..127, 16B chunk 0..7 within 128B
        int sw = (ck * 16) ^ ((r & 7) * 16);
        CP_ASYNC16(ab + r * 128 + sw, A + (size_t)r * NC + kchunk * 128 + ck * 16);
        CP_ASYNC16(bb + r * 128 + sw, B + (size_t)r * NC + kchunk * 128 + ck * 16);
    }
}

__global__ void __launch_bounds__(256) vq_gemm() {
    extern __shared__ char smem[];
    const uint32_t sb = smem_u32(smem);
    const int t = threadIdx.x;
    const int lane = t & 31, wid = t >> 5;
    const int warp_m = wid >> 1, warp_n = wid & 1;   // 4x2 warps -> 32x64 per warp
    const int col0 = blockIdx.x * TN;
    const int row0 = blockIdx.y * TM;
    const signed char* A = g_az + (size_t)row0 * NC;
    const signed char* B = g_bq + (size_t)col0 * NC;

    int d[2][8][4];
#pragma unroll
    for (int i = 0; i < 2; i++)
#pragma unroll
        for (int j = 0; j < 8; j++)
#pragma unroll
            for (int q = 0; q < 4; q++) d[i][j][q] = 0;

    issue_loads(sb, 0, A, B, 0, t);
    CP_COMMIT();

    for (int kc = 0; kc < 2; kc++) {
        if (kc < 1) {
            issue_loads(sb, 1, A, B, 1, t);
            CP_COMMIT();
            CP_WAIT(1);
        } else {
            CP_WAIT(0);
        }
        __syncthreads();

        const uint32_t Ab = sb + kc * 32768;
        const uint32_t Bb = Ab + 16384;
#pragma unroll
        for (int ks = 0; ks < 4; ks++) {              // k32 per step, 4 steps = k128
            const int c2 = ks * 32 + (lane >> 4) * 16;
            uint32_t a[2][4];
#pragma unroll
            for (int mt = 0; mt < 2; mt++) {
                int row = warp_m * 32 + mt * 16 + (lane & 15);
                uint32_t ad = Ab + row * 128 + (c2 ^ ((row & 7) * 16));
                LDSM_X4(a[mt][0], a[mt][1], a[mt][2], a[mt][3], ad);
            }
            uint32_t bq[4][4];
#pragma unroll
            for (int np = 0; np < 4; np++) {
                int brow = warp_n * 64 + np * 16 + (lane & 15);
                uint32_t bd = Bb + brow * 128 + (c2 ^ ((brow & 7) * 16));
                LDSM_X4(bq[np][0], bq[np][1], bq[np][2], bq[np][3], bd);
            }
#pragma unroll
            for (int mt = 0; mt < 2; mt++)
#pragma unroll
                for (int np = 0; np < 4; np++) {
                    IMMA16832(d[mt][np * 2],     a[mt][0], a[mt][1], a[mt][2], a[mt][3],
                              bq[np][0], bq[np][2]);
                    IMMA16832(d[mt][np * 2 + 1], a[mt][0], a[mt][1], a[mt][2], a[mt][3],
                              bq[np][1], bq[np][3]);
                }
        }
        __syncthreads();
    }

    // epilogue: float(acc)*ss + |cb|^2 -> bf16, stage in smem, coalesced store
    const float ss = g_ss;
    unsigned short* S = (unsigned short*)smem;
    const int g = lane >> 2, tig = lane & 3;
#pragma unroll
    for (int mt = 0; mt < 2; mt++) {
        const int rbase = warp_m * 32 + mt * 16 + g;
#pragma unroll
        for (int nt = 0; nt < 8; nt++) {
            const int scol = warp_n * 64 + nt * 8 + 2 * tig;
            const float cn0 = __ldg(&g_cn[col0 + scol]);
            const float cn1 = __ldg(&g_cn[col0 + scol + 1]);
#pragma unroll
            for (int half = 0; half < 2; half++) {
                float v0 = (float)d[mt][nt][2 * half + 0] * ss + cn0;
                float v1 = (float)d[mt][nt][2 * half + 1] * ss + cn1;
                uint32_t pk;
                asm("cvt.rn.satfinite.bf16x2.f32 %0, %1, %2;" : "=r"(pk) : "f"(v1), "f"(v0));
                *(uint32_t*)(S + (rbase + half * 8) * 136 + scol) = pk;
            }
        }
    }
    __syncthreads();
#pragma unroll
    for (int i = 0; i < 8; i++) {
        int e = i * 256 + t;
        int r = e >> 4, ch = e & 15;
        uint4 v = *(const uint4*)(S + r * 136 + ch * 8);
        *(uint4*)(g_dist + (size_t)(row0 + r) * NK + col0 + ch * 8) = v;
    }
}

// ---------------- scan + exact fp32 refine ----------------
__global__ void __launch_bounds__(256) vq_scan(const float* __restrict__ cb) {
    const int row = blockIdx.x, t = threadIdx.x;
    const uint4* rp = (const uint4*)(g_dist + (size_t)row * NK);
    uint4 v[4];
#pragma unroll
    for (int i = 0; i < 4; i++) v[i] = rp[i * 256 + t];   // coalesced

    float loc = FLT_MAX;
#pragma unroll
    for (int i = 0; i < 4; i++) {
        const unsigned* u = (const unsigned*)&v[i];
#pragma unroll
        for (int j = 0; j < 4; j++) {
            __nv_bfloat162 p = *(const __nv_bfloat162*)&u[j];
            loc = fminf(loc, fminf(__low2float(p), __high2float(p)));
        }
    }
    __shared__ float sred[256];
    sred[t] = loc;
    __syncthreads();
    for (int s = 128; s > 0; s >>= 1) { if (t < s) sred[t] = fminf(sred[t], sred[t + s]); __syncthreads(); }
    const float thr = sred[0] + MARGIN;
    __syncthreads();

    __shared__ int scnt;
    __shared__ int scand[64];
    if (t == 0) scnt = 0;
    __syncthreads();
#pragma unroll
    for (int i = 0; i < 4; i++) {
        const unsigned* u = (const unsigned*)&v[i];
#pragma unroll
        for (int j = 0; j < 4; j++) {
            __nv_bfloat162 p = *(const __nv_bfloat162*)&u[j];
            float a = __low2float(p), b = __high2float(p);
            int base = (i * 256 + t) * 8 + j * 2;
            if (a <= thr) { int s0 = atomicAdd(&scnt, 1); if (s0 < 64) scand[s0] = base; }
            if (b <= thr) { int s1 = atomicAdd(&scnt, 1); if (s1 < 64) scand[s1] = base + 1; }
        }
    }
    __syncthreads();
    const int cnt = min(scnt, 64);

    __shared__ float sbv;
    __shared__ int sbi;
    if (t == 0) { sbv = FLT_MAX; sbi = 0x7fffffff; }
    __syncthreads();
    const float zt = g_zf[(size_t)row * NC + t];
    const float zn = g_zn[row];
    for (int c = 0; c < cnt; c++) {
        const int k = scand[c];
        float pv = zt * (-2.0f * cb[(size_t)k * NC + t]);
        sred[t] = pv;
        __syncthreads();
        for (int s = 128; s > 0; s >>= 1) { if (t < s) sred[t] += sred[t + s]; __syncthreads(); }
        if (t == 0) {
            float dd = (sred[0] + zn) + g_cn[k];
            if (dd < sbv || (dd == sbv && k < sbi)) { sbv = dd; sbi = k; }
        }
        __syncthreads();
    }
    if (t == 0) g_idx[row] = sbi;
}

// ---------------- outputs ----------------
__global__ void vq_gather(const float* __restrict__ cb, float* __restrict__ out) {
    int o = blockIdx.x * blockDim.x + threadIdx.x;
    int w = o & 31;
    int h = (o >> 5) & 31;
    int c = (o >> 10) & 255;
    int b = o >> 18;
    int n = (b << 10) + (h << 5) + w;
    out[o] = cb[(size_t)g_idx[n] * NC + c];
}

__global__ void vq_idx_out(float* __restrict__ out) {
    int n = blockIdx.x * blockDim.x + threadIdx.x;
    out[ZQ_ELEMS + n] = (float)g_idx[n];
}

extern "C" void kernel_launch(void* const* d_in, const int* in_sizes, int n_in,
                              void* d_out, int out_size) {
    const float* z  = (const float*)d_in[0];
    const float* cb = (const float*)d_in[1];
    if (n_in >= 2 && in_sizes[0] == NK * NC && in_sizes[1] == NPTS * NC) {
        const float* tmp = z; z = cb; cb = tmp;
    }
    float* out = (float*)d_out;

    cudaFuncSetAttribute(vq_gemm, cudaFuncAttributeMaxDynamicSharedMemorySize, 65536);

    k_init<<<1, 1>>>();
    k_max<<<2048, 256>>>(z, cb);
    k_scales<<<1, 1>>>();
    prep_cb<<<NK, 256>>>(cb);
    prep_z<<<NPTS / 256, 256>>>(z);
    vq_gemm<<<dim3(NK / TN, NPTS / TM), 256, 65536>>>();
    vq_scan<<<NPTS, 256>>>(cb);
    vq_gather<<<ZQ_ELEMS / 256, 256>>>(cb, out);
    if (out_size >= ZQ_ELEMS + NPTS)
        vq_idx_out<<<NPTS / 256, 256>>>(out);
}

// round 6
// speedup vs baseline: 2.0605x; 1.9682x over previous
#include <cuda_runtime.h>
#include <cuda_bf16.h>
#include <float.h>
#include <stdint.h>

// VectorQuantize: z[16,256,32,32] f32, codebook[8192,256] f32
// bf16 mma.sync GEMM -> per-(row,tile) fp32 min + 128-bit candidate mask
// -> warp/row select + exact fp32 refine. No dense score matrix.

#define NPTS 16384
#define NC   256
#define NK   8192
#define ZQ_ELEMS 4194304
#define TM 128
#define TN 128
#define NTILE (NK / TN)      // 64
#define MARGIN 8e-3f

// ---------------- scratch ----------------
__device__ unsigned short g_ah[NPTS * NC];    // bf16(z)
__device__ unsigned short g_bh[NK * NC];      // bf16(-2cb)
__device__ float g_zf[NPTS * NC];             // fp32 z rows (refine)
__device__ float g_zn[NPTS];
__device__ float g_cn[NK];                    // |cb|^2
__device__ float g_tmin[(size_t)NPTS * NTILE];          // per (row,tile) min
__device__ unsigned g_tmask[(size_t)NPTS * NTILE * 4];  // per (row,tile) 128-bit mask
__device__ int g_idx[NPTS];

// smem layout for vq_gemm
#define SROWMIN 65536   // 128 x u32
#define SMASK   66048   // 128 x 4 x u32
#define SMEM_SZ 68608

// ---------------- PTX helpers ----------------
__device__ __forceinline__ uint32_t smem_u32(const void* p) {
    uint32_t a;
    asm("{ .reg .u64 t; cvta.to.shared.u64 t, %1; cvt.u32.u64 %0, t; }" : "=r"(a) : "l"(p));
    return a;
}
#define CP_ASYNC16(sm, gp) \
    asm volatile("cp.async.cg.shared.global [%0], [%1], 16;" :: "r"(sm), "l"(gp) : "memory")
#define CP_COMMIT() asm volatile("cp.async.commit_group;" ::: "memory")
#define CP_WAIT(n)  asm volatile("cp.async.wait_group %0;" :: "n"(n) : "memory")
#define LDSM_X4(r0, r1, r2, r3, ad) \
    asm volatile("ldmatrix.sync.aligned.m8n8.x4.shared.b16 {%0,%1,%2,%3}, [%4];" \
                 : "=r"(r0), "=r"(r1), "=r"(r2), "=r"(r3) : "r"(ad))
#define MMA16816(d, a0, a1, a2, a3, b0, b1) \
    asm volatile("mma.sync.aligned.m16n8k16.row.col.f32.bf16.bf16.f32 " \
                 "{%0,%1,%2,%3}, {%4,%5,%6,%7}, {%8,%9}, {%0,%1,%2,%3};" \
                 : "+f"((d)[0]), "+f"((d)[1]), "+f"((d)[2]), "+f"((d)[3]) \
                 : "r"(a0), "r"(a1), "r"(a2), "r"(a3), "r"(b0), "r"(b1))

__device__ __forceinline__ uint32_t fenc(float f) {
    uint32_t b = __float_as_uint(f);
    return (b & 0x80000000u) ? ~b : (b | 0x80000000u);
}
__device__ __forceinline__ float fdec(uint32_t u) {
    uint32_t b = (u & 0x80000000u) ? (u & 0x7FFFFFFFu) : ~u;
    return __uint_as_float(b);
}

// ---------------- prep ----------------
__global__ void prep_cb(const float* __restrict__ cb) {
    int k = blockIdx.x, t = threadIdx.x;
    float v = cb[(size_t)k * NC + t];
    __nv_bfloat16 h = __float2bfloat16_rn(-2.0f * v);
    g_bh[k * NC + t] = *(unsigned short*)&h;
    __shared__ float red[256];
    red[t] = v * v;
    __syncthreads();
    for (int s = 128; s > 0; s >>= 1) { if (t < s) red[t] += red[t + s]; __syncthreads(); }
    if (t == 0) g_cn[k] = red[0];
}

__global__ void prep_z(const float* __restrict__ z) {
    int n = blockIdx.x * blockDim.x + threadIdx.x;
    int b = n >> 10, hw = n & 1023;
    const float* zp = z + (size_t)b * (NC * 1024) + hw;
    float acc = 0.f;
#pragma unroll 8
    for (int c = 0; c < NC; c++) {
        float v = zp[(size_t)c * 1024];
        g_zf[n * NC + c] = v;
        acc += v * v;
        __nv_bfloat16 h = __float2bfloat16_rn(v);
        g_ah[n * NC + c] = *(unsigned short*)&h;
    }
    g_zn[n] = acc;
}

// ---------------- GEMM (R3-identical mainloop) + summary epilogue ----------------
__device__ __forceinline__ void issue_loads(uint32_t sb, int buf,
                                            const unsigned short* A, const unsigned short* B,
                                            int kchunk, int t) {
    uint32_t ab = sb + buf * 32768;
    uint32_t bb = ab + 16384;
#pragma unroll
    for (int i = 0; i < 4; i++) {
        int e = i * 256 + t;
        int r = e >> 3, ck = e & 7;
        int sw = (ck * 16) ^ ((r & 7) * 16);
        CP_ASYNC16(ab + r * 128 + sw, A + (size_t)r * NC + kchunk * 64 + ck * 8);
        CP_ASYNC16(bb + r * 128 + sw, B + (size_t)r * NC + kchunk * 64 + ck * 8);
    }
}

__global__ void __launch_bounds__(256) vq_gemm() {
    extern __shared__ char smem[];
    const uint32_t sb = smem_u32(smem);
    const int t = threadIdx.x;
    const int lane = t & 31, wid = t >> 5;
    const int warp_m = wid >> 1, warp_n = wid & 1;   // 4x2 warps -> 32x64 per warp
    const int tile = blockIdx.x;
    const int col0 = tile * TN;
    const int row0 = blockIdx.y * TM;
    const unsigned short* A = g_ah + (size_t)row0 * NC;
    const unsigned short* B = g_bh + (size_t)col0 * NC;

    uint32_t* rowmin = (uint32_t*)(smem + SROWMIN);
    uint32_t* maskw  = (uint32_t*)(smem + SMASK);
    if (t < TM) rowmin[t] = fenc(FLT_MAX);
    maskw[t] = 0; maskw[t + 256] = 0;

    float d[2][8][4];
#pragma unroll
    for (int i = 0; i < 2; i++)
#pragma unroll
        for (int j = 0; j < 8; j++)
#pragma unroll
            for (int q = 0; q < 4; q++) d[i][j][q] = 0.f;

    issue_loads(sb, 0, A, B, 0, t);
    CP_COMMIT();

    for (int kc = 0; kc < 4; kc++) {
        if (kc < 3) {
            issue_loads(sb, (kc + 1) & 1, A, B, kc + 1, t);
            CP_COMMIT();
            CP_WAIT(1);
        } else {
            CP_WAIT(0);
        }
        __syncthreads();

        const uint32_t Ab = sb + (kc & 1) * 32768;
        const uint32_t Bb = Ab + 16384;
#pragma unroll
        for (int ks = 0; ks < 4; ks++) {
            const int c2 = ks * 32 + (lane >> 4) * 16;
            uint32_t a[2][4];
#pragma unroll
            for (int mt = 0; mt < 2; mt++) {
                int row = warp_m * 32 + mt * 16 + (lane & 15);
                uint32_t ad = Ab + row * 128 + (c2 ^ ((row & 7) * 16));
                LDSM_X4(a[mt][0], a[mt][1], a[mt][2], a[mt][3], ad);
            }
            uint32_t bq[4][4];
#pragma unroll
            for (int np = 0; np < 4; np++) {
                int brow = warp_n * 64 + np * 16 + (lane & 15);
                uint32_t bd = Bb + brow * 128 + (c2 ^ ((brow & 7) * 16));
                LDSM_X4(bq[np][0], bq[np][1], bq[np][2], bq[np][3], bd);
            }
#pragma unroll
            for (int mt = 0; mt < 2; mt++)
#pragma unroll
                for (int np = 0; np < 4; np++) {
                    MMA16816(d[mt][np * 2],     a[mt][0], a[mt][1], a[mt][2], a[mt][3],
                             bq[np][0], bq[np][2]);
                    MMA16816(d[mt][np * 2 + 1], a[mt][0], a[mt][1], a[mt][2], a[mt][3],
                             bq[np][1], bq[np][3]);
                }
        }
        __syncthreads();
    }

    // ---- summary epilogue ----
    const int g = lane >> 2, tig = lane & 3;
    // add |cb|^2 into scores
#pragma unroll
    for (int nt = 0; nt < 8; nt++) {
        const int scol = col0 + warp_n * 64 + nt * 8 + 2 * tig;
        const float cn0 = __ldg(&g_cn[scol]);
        const float cn1 = __ldg(&g_cn[scol + 1]);
#pragma unroll
        for (int mt = 0; mt < 2; mt++) {
            d[mt][nt][0] += cn0; d[mt][nt][1] += cn1;
            d[mt][nt][2] += cn0; d[mt][nt][3] += cn1;
        }
    }
    // pass 1: per-row tile min
#pragma unroll
    for (int mt = 0; mt < 2; mt++) {
        const int r0 = warp_m * 32 + mt * 16 + g;
        float mn0 = FLT_MAX, mn1 = FLT_MAX;
#pragma unroll
        for (int nt = 0; nt < 8; nt++) {
            mn0 = fminf(mn0, fminf(d[mt][nt][0], d[mt][nt][1]));
            mn1 = fminf(mn1, fminf(d[mt][nt][2], d[mt][nt][3]));
        }
        atomicMin(&rowmin[r0],     fenc(mn0));
        atomicMin(&rowmin[r0 + 8], fenc(mn1));
    }
    __syncthreads();
    // pass 2: candidate mask
#pragma unroll
    for (int mt = 0; mt < 2; mt++) {
        const int r0 = warp_m * 32 + mt * 16 + g;
        const float th0 = fdec(rowmin[r0]) + MARGIN;
        const float th1 = fdec(rowmin[r0 + 8]) + MARGIN;
#pragma unroll
        for (int nt = 0; nt < 8; nt++) {
            const int c = warp_n * 64 + nt * 8 + 2 * tig;   // col within tile, 0..127
            if (d[mt][nt][0] <= th0) atomicOr(&maskw[r0 * 4 + (c >> 5)], 1u << (c & 31));
            if (d[mt][nt][1] <= th0) atomicOr(&maskw[r0 * 4 + ((c + 1) >> 5)], 1u << ((c + 1) & 31));
            if (d[mt][nt][2] <= th1) atomicOr(&maskw[(r0 + 8) * 4 + (c >> 5)], 1u << (c & 31));
            if (d[mt][nt][3] <= th1) atomicOr(&maskw[(r0 + 8) * 4 + ((c + 1) >> 5)], 1u << ((c + 1) & 31));
        }
    }
    __syncthreads();
    // writeout summaries
    if (t < TM) g_tmin[(size_t)(row0 + t) * NTILE + tile] = fdec(rowmin[t]);
#pragma unroll
    for (int i = 0; i < 2; i++) {
        int e = i * 256 + t;         // 0..511
        int r = e >> 2, w = e & 3;
        g_tmask[((size_t)(row0 + r) * NTILE + tile) * 4 + w] = maskw[r * 4 + w];
    }
}

// ---------------- select + exact fp32 refine: one warp per row ----------------
__global__ void __launch_bounds__(256) vq_select(const float* __restrict__ cb) {
    const int lane = threadIdx.x & 31;
    const int row = blockIdx.x * 8 + (threadIdx.x >> 5);

    const float* tm = g_tmin + (size_t)row * NTILE;
    const float v0 = tm[lane], v1 = tm[lane + 32];
    float m = fminf(v0, v1);
#pragma unroll
    for (int o = 16; o > 0; o >>= 1) m = fminf(m, __shfl_xor_sync(0xffffffffu, m, o));
    const float thr = m + MARGIN;

    float z8[8];
#pragma unroll
    for (int i = 0; i < 8; i++) z8[i] = g_zf[(size_t)row * NC + lane * 8 + i];
    const float zn = g_zn[row];

    float bv = FLT_MAX;
    int bi = 0x7fffffff;

    unsigned bal[2];
    bal[0] = __ballot_sync(0xffffffffu, v0 <= thr);
    bal[1] = __ballot_sync(0xffffffffu, v1 <= thr);
#pragma unroll
    for (int p = 0; p < 2; p++) {
        unsigned bits = bal[p];
        while (bits) {
            const int tile = p * 32 + (__ffs(bits) - 1);
            bits &= bits - 1;
            const uint4 mk = *(const uint4*)(g_tmask + ((size_t)row * NTILE + tile) * 4);
            unsigned w[4] = { mk.x, mk.y, mk.z, mk.w };
#pragma unroll
            for (int wi = 0; wi < 4; wi++) {
                unsigned ww = w[wi];
                while (ww) {
                    const int b = __ffs(ww) - 1;
                    ww &= ww - 1;
                    const int k = tile * TN + wi * 32 + b;
                    const float* cbr = cb + (size_t)k * NC + lane * 8;
                    float s = 0.f;
#pragma unroll
                    for (int i = 0; i < 8; i++) s = fmaf(z8[i], -2.0f * cbr[i], s);
#pragma unroll
                    for (int o = 16; o > 0; o >>= 1) s += __shfl_xor_sync(0xffffffffu, s, o);
                    const float dd = (s + zn) + g_cn[k];
                    if (dd < bv || (dd == bv && k < bi)) { bv = dd; bi = k; }
                }
            }
        }
    }
    if (lane == 0) g_idx[row] = bi;
}

// ---------------- outputs ----------------
__global__ void vq_gather(const float* __restrict__ cb, float* __restrict__ out) {
    int o = blockIdx.x * blockDim.x + threadIdx.x;
    int w = o & 31;
    int h = (o >> 5) & 31;
    int c = (o >> 10) & 255;
    int b = o >> 18;
    int n = (b << 10) + (h << 5) + w;
    out[o] = cb[(size_t)g_idx[n] * NC + c];
}

__global__ void vq_idx_out(float* __restrict__ out) {
    int n = blockIdx.x * blockDim.x + threadIdx.x;
    out[ZQ_ELEMS + n] = (float)g_idx[n];
}

extern "C" void kernel_launch(void* const* d_in, const int* in_sizes, int n_in,
                              void* d_out, int out_size) {
    const float* z  = (const float*)d_in[0];
    const float* cb = (const float*)d_in[1];
    if (n_in >= 2 && in_sizes[0] == NK * NC && in_sizes[1] == NPTS * NC) {
        const float* tmp = z; z = cb; cb = tmp;
    }
    float* out = (float*)d_out;

    cudaFuncSetAttribute(vq_gemm, cudaFuncAttributeMaxDynamicSharedMemorySize, SMEM_SZ);

    prep_cb<<<NK, 256>>>(cb);
    prep_z<<<NPTS / 256, 256>>>(z);
    vq_gemm<<<dim3(NK / TN, NPTS / TM), 256, SMEM_SZ>>>();
    vq_select<<<NPTS / 8, 256>>>(cb);
    vq_gather<<<ZQ_ELEMS / 256, 256>>>(cb, out);
    if (out_size >= ZQ_ELEMS + NPTS)
        vq_idx_out<<<NPTS / 256, 256>>>(out);
}